// round 5
// baseline (speedup 1.0000x reference)
#include <cuda_runtime.h>
#include <math.h>

#define H 2048
#define N 16384
#define D 1024
#define EPSV 1e-8f
#define DIMSZ (5 + 3*D)   // 3077
#define UB 1024           // k_update blocks
#define RPB (N / UB)      // 16 rows per update block

// ---- scratch (__device__ globals; no allocs allowed) ----
__device__ float g_dim5[5];          // beta, gamma, shift logits
__device__ float g_k[D];
__device__ float g_erase[D];
__device__ float g_add[D];
__device__ float g_s[N];             // exp(beta*sim)  (no max-sub; bounded)
__device__ float g_gate[N];
__device__ float g_wp[N];            // unnormalized w_tilde^gamma
__device__ float g_pp[64];           // per-block pow-sum partials
__device__ float g_part[UB * D];     // per-block memory_read partials (4 MB)

__device__ __forceinline__ float warp_sum(float v) {
#pragma unroll
    for (int o = 16; o; o >>= 1) v += __shfl_xor_sync(0xffffffffu, v, o);
    return v;
}

// ---------------------------------------------------------------------------
// dim_out = W_dim @ hidden + b_dim, scattered into g_dim5/g_k/g_erase/g_add.
// <<<DIMSZ, 256>>>
// ---------------------------------------------------------------------------
__global__ void k_dim(const float* __restrict__ W, const float* __restrict__ h,
                      const float* __restrict__ b) {
    int row = blockIdx.x;
    const float4* w4 = reinterpret_cast<const float4*>(W + (size_t)row * H);
    const float4* h4 = reinterpret_cast<const float4*>(h);
    float s = 0.f;
#pragma unroll 2
    for (int j = threadIdx.x; j < H / 4; j += 256) {
        float4 w = w4[j], x = h4[j];
        s += w.x * x.x + w.y * x.y + w.z * x.z + w.w * x.w;
    }
    __shared__ float red[8];
    s = warp_sum(s);
    if ((threadIdx.x & 31) == 0) red[threadIdx.x >> 5] = s;
    __syncthreads();
    if (threadIdx.x == 0) {
        float v = 0.f;
#pragma unroll
        for (int i = 0; i < 8; i++) v += red[i];
        v += b[row];
        if (row < 5)              g_dim5[row] = v;
        else if (row < 5 + D)     g_k[row - 5] = v;
        else if (row < 5 + 2*D)   g_erase[row - 5 - D] = v;
        else                      g_add[row - 5 - 2*D] = v;
    }
}

// ---------------------------------------------------------------------------
// Fused heavy pass, WARP-PER-ROW (no smem, no block barriers):
//   warp w handles row w: dot(mem,k), ||mem||^2, ||k||^2, gate GEMV
//   -> g_s[row] = exp(beta*cos_sim), g_gate[row] = sigmoid.
// 8 warps/block, grid N/8 = 2048. <<<N/8, 256>>>
// ---------------------------------------------------------------------------
__global__ void __launch_bounds__(256) k_row(const float* __restrict__ mem,
                                             const float* __restrict__ Wg,
                                             const float* __restrict__ h,
                                             const float* __restrict__ bg) {
    int row  = (blockIdx.x << 3) + (threadIdx.x >> 5);
    int lane = threadIdx.x & 31;
    const float4* m4 = reinterpret_cast<const float4*>(mem + (size_t)row * D);
    const float4* k4 = reinterpret_cast<const float4*>(g_k);

    // memory/key pass: 8 float4 per lane, front-batched
    float4 mv[8], kv[8];
#pragma unroll
    for (int u = 0; u < 8; u++) mv[u] = m4[lane + 32 * u];
#pragma unroll
    for (int u = 0; u < 8; u++) kv[u] = k4[lane + 32 * u];
    float d1 = 0.f, d2 = 0.f, d4 = 0.f;
#pragma unroll
    for (int u = 0; u < 8; u++) {
        d1 += mv[u].x * kv[u].x + mv[u].y * kv[u].y
            + mv[u].z * kv[u].z + mv[u].w * kv[u].w;
        d2 += mv[u].x * mv[u].x + mv[u].y * mv[u].y
            + mv[u].z * mv[u].z + mv[u].w * mv[u].w;
        d4 += kv[u].x * kv[u].x + kv[u].y * kv[u].y
            + kv[u].z * kv[u].z + kv[u].w * kv[u].w;
    }

    // gate GEMV: 16 float4 of Wg per lane (2 batches of 8), h is L1-hot
    const float4* w4 = reinterpret_cast<const float4*>(Wg + (size_t)row * H);
    const float4* h4 = reinterpret_cast<const float4*>(h);
    float d3 = 0.f;
#pragma unroll
    for (int b = 0; b < 2; b++) {
        float4 wv[8], xv[8];
#pragma unroll
        for (int u = 0; u < 8; u++) wv[u] = w4[lane + 32 * (8 * b + u)];
#pragma unroll
        for (int u = 0; u < 8; u++) xv[u] = h4[lane + 32 * (8 * b + u)];
#pragma unroll
        for (int u = 0; u < 8; u++)
            d3 += wv[u].x * xv[u].x + wv[u].y * xv[u].y
                + wv[u].z * xv[u].z + wv[u].w * xv[u].w;
    }

    d1 = warp_sum(d1); d2 = warp_sum(d2); d3 = warp_sum(d3); d4 = warp_sum(d4);
    if (lane == 0) {
        float sim = d1 / (sqrtf(d2) * sqrtf(d4) + EPSV);
        g_s[row] = expf(g_dim5[0] * sim);      // bounded: |beta*sim| small
        g_gate[row] = 1.f / (1.f + expf(-(d3 + bg[row])));
    }
}

// ---------------------------------------------------------------------------
// Shift conv + pow. Each of 64 blocks reduces the full softmax denominator
// (L2-resident, deterministic), then computes w_tilde^gamma for its 256
// indices; writes g_wp and a per-block pow-sum partial. <<<64, 256>>>
// ---------------------------------------------------------------------------
__device__ __forceinline__ float wg_at(int j, float inv_sum,
                                       const float* __restrict__ lw) {
    j &= (N - 1);
    float g = g_gate[j];
    return g * g_s[j] * inv_sum + (1.f - g) * lw[j];
}

__global__ void k_shift(const float* __restrict__ lw) {
    int t = threadIdx.x;
    __shared__ float red[8];
    __shared__ float bcast;

    float s = 0.f;
#pragma unroll 8
    for (int j = t; j < N; j += 256) s += g_s[j];
    s = warp_sum(s);
    if ((t & 31) == 0) red[t >> 5] = s;
    __syncthreads();
    if (t == 0) {
        float v = 0.f;
#pragma unroll
        for (int i = 0; i < 8; i++) v += red[i];
        bcast = 1.f / v;
    }
    __syncthreads();
    float inv_sum = bcast;

    float a0 = g_dim5[2], a1 = g_dim5[3], a2 = g_dim5[4];
    float mm = fmaxf(a0, fmaxf(a1, a2));
    float e0 = expf(a0 - mm), e1 = expf(a1 - mm), e2 = expf(a2 - mm);
    float inv3 = 1.f / (e0 + e1 + e2);
    float sh0 = e0 * inv3, sh1 = e1 * inv3, sh2 = e2 * inv3;
    float gamma = g_dim5[1];

    int i = blockIdx.x * 256 + t;
    float wt = sh0 * wg_at(i - 1, inv_sum, lw)
             + sh1 * wg_at(i,     inv_sum, lw)
             + sh2 * wg_at(i + 1, inv_sum, lw);
    float wp = powf(wt, gamma);
    g_wp[i] = wp;

    __syncthreads();
    float p = warp_sum(wp);
    if ((t & 31) == 0) red[t >> 5] = p;
    __syncthreads();
    if (t == 0) {
        float v = 0.f;
#pragma unroll
        for (int i2 = 0; i2 < 8; i2++) v += red[i2];
        g_pp[blockIdx.x] = v;                 // deterministic partial
    }
}

// ---------------------------------------------------------------------------
// new_memory + weight output + memory_read PARTIALS (no atomics).
// 1024 blocks x 256 threads; block handles 16 rows; thread owns 1 float4 col.
// All w values preloaded to smem; m loads batched 8 rows deep.
// <<<UB, 256>>>
// ---------------------------------------------------------------------------
__global__ void __launch_bounds__(256) k_update(const float* __restrict__ mem,
                                                float* __restrict__ out) {
    int t = threadIdx.x;                       // 0..255 -> cols 4t..4t+3
    __shared__ float red2[2];
    __shared__ float w_s[RPB];
    // reduce 64 pow-sum partials -> inv
    float v = (t < 64) ? g_pp[t] : 0.f;
    v = warp_sum(v);
    if ((t & 31) == 0 && t < 64) red2[t >> 5] = v;
    __syncthreads();
    if (t == 0) red2[0] = 1.f / (red2[0] + red2[1]);
    __syncthreads();
    float inv = red2[0];

    int base = blockIdx.x * RPB;
    if (t < RPB) {
        float wv = g_wp[base + t] * inv;
        w_s[t] = wv;
        out[D + base + t] = wv;                // weight output
    }
    __syncthreads();

    float4* newm = reinterpret_cast<float4*>(out + D + N);
    const float4* m4 = reinterpret_cast<const float4*>(mem);
    float4 e4 = reinterpret_cast<const float4*>(g_erase)[t];
    float4 a4 = reinterpret_cast<const float4*>(g_add)[t];
    float4 acc = make_float4(0.f, 0.f, 0.f, 0.f);

#pragma unroll
    for (int r0 = 0; r0 < RPB; r0 += 8) {
        float4 m[8];
#pragma unroll
        for (int u = 0; u < 8; u++)
            m[u] = m4[(size_t)(base + r0 + u) * 256 + t];
#pragma unroll
        for (int u = 0; u < 8; u++) {
            float w = w_s[r0 + u];
            acc.x += w * m[u].x; acc.y += w * m[u].y;
            acc.z += w * m[u].z; acc.w += w * m[u].w;
            float4 nm;
            nm.x = m[u].x * (1.f - w * e4.x) + w * a4.x;
            nm.y = m[u].y * (1.f - w * e4.y) + w * a4.y;
            nm.z = m[u].z * (1.f - w * e4.z) + w * a4.z;
            nm.w = m[u].w * (1.f - w * e4.w) + w * a4.w;
            newm[(size_t)(base + r0 + u) * 256 + t] = nm;
        }
    }
    reinterpret_cast<float4*>(g_part + (size_t)blockIdx.x * D)[t] = acc;
}

// ---------------------------------------------------------------------------
// Fold UB partials per column into memory_read. <<<D/128, 128>>>
// ---------------------------------------------------------------------------
__global__ void k_read(float* __restrict__ out) {
    int col = blockIdx.x * 128 + threadIdx.x;
    float s = 0.f;
#pragma unroll 8
    for (int b = 0; b < UB; b++) s += g_part[(size_t)b * D + col];
    out[col] = s;
}

// ---------------------------------------------------------------------------
extern "C" void kernel_launch(void* const* d_in, const int* in_sizes, int n_in,
                              void* d_out, int out_size) {
    const float* hidden = (const float*)d_in[0];
    const float* lw     = (const float*)d_in[1];
    const float* mem    = (const float*)d_in[2];
    const float* Wd     = (const float*)d_in[3];
    const float* bd     = (const float*)d_in[4];
    const float* Wg     = (const float*)d_in[5];
    const float* bg     = (const float*)d_in[6];
    float* out = (float*)d_out;

    k_dim   <<<DIMSZ, 256>>>(Wd, hidden, bd);
    k_row   <<<N / 8, 256>>>(mem, Wg, hidden, bg);
    k_shift <<<64, 256>>>(lw);
    k_update<<<UB, 256>>>(mem, out);
    k_read  <<<D / 128, 128>>>(out);
}

// round 6
// speedup vs baseline: 1.0511x; 1.0511x over previous
#include <cuda_runtime.h>
#include <math.h>

#define H 2048
#define N 16384
#define D 1024
#define EPSV 1e-8f
#define DIMSZ (5 + 3*D)   // 3077
#define UB 512            // k_update blocks
#define RPB (N / UB)      // 32 rows per update block
#define RB 512            // k_row blocks: 8 warps x 4 rows = 32 rows/block

// ---- scratch (__device__ globals; no allocs allowed) ----
__device__ float g_dim5[5];          // beta, gamma, shift logits
__device__ float g_k[D];
__device__ float g_erase[D];
__device__ float g_add[D];
__device__ float g_s[N];             // exp(beta*sim)  (no max-sub; bounded)
__device__ float g_gate[N];
__device__ float g_wp[N];            // unnormalized w_tilde^gamma
__device__ float g_pp[64];           // per-block pow-sum partials
__device__ float g_part[UB * D];     // per-block memory_read partials (2 MB)

__device__ __forceinline__ float warp_sum(float v) {
#pragma unroll
    for (int o = 16; o; o >>= 1) v += __shfl_xor_sync(0xffffffffu, v, o);
    return v;
}
__device__ __forceinline__ float dot4(float4 a, float4 b) {
    return a.x * b.x + a.y * b.y + a.z * b.z + a.w * b.w;
}

// ---------------------------------------------------------------------------
// dim_out = W_dim @ hidden + b_dim, scattered into g_dim5/g_k/g_erase/g_add.
// <<<DIMSZ, 256>>>
// ---------------------------------------------------------------------------
__global__ void k_dim(const float* __restrict__ W, const float* __restrict__ h,
                      const float* __restrict__ b) {
    int row = blockIdx.x;
    const float4* w4 = reinterpret_cast<const float4*>(W + (size_t)row * H);
    const float4* h4 = reinterpret_cast<const float4*>(h);
    float s = 0.f;
#pragma unroll 2
    for (int j = threadIdx.x; j < H / 4; j += 256) {
        float4 w = w4[j], x = h4[j];
        s += dot4(w, x);
    }
    __shared__ float red[8];
    s = warp_sum(s);
    if ((threadIdx.x & 31) == 0) red[threadIdx.x >> 5] = s;
    __syncthreads();
    if (threadIdx.x == 0) {
        float v = 0.f;
#pragma unroll
        for (int i = 0; i < 8; i++) v += red[i];
        v += b[row];
        if (row < 5)              g_dim5[row] = v;
        else if (row < 5 + D)     g_k[row - 5] = v;
        else if (row < 5 + 2*D)   g_erase[row - 5 - D] = v;
        else                      g_add[row - 5 - 2*D] = v;
    }
}

// ---------------------------------------------------------------------------
// Fused heavy pass v3: k and h staged in SMEM once per block (amortizes their
// L2 traffic 32x); 8 warps x 4 rows each, warp-shuffle reductions only.
// Loads chunked 4-deep (bounded register pressure).
// <<<RB, 256>>>
// ---------------------------------------------------------------------------
__global__ void __launch_bounds__(256) k_row(const float* __restrict__ mem,
                                             const float* __restrict__ Wg,
                                             const float* __restrict__ h,
                                             const float* __restrict__ bg) {
    __shared__ float4 sk[D / 4];     // 4 KB
    __shared__ float4 sh[H / 4];     // 8 KB
    int t = threadIdx.x;
    sk[t] = reinterpret_cast<const float4*>(g_k)[t];
    {
        const float4* h4 = reinterpret_cast<const float4*>(h);
        sh[t] = h4[t];
        sh[t + 256] = h4[t + 256];
    }
    __syncthreads();

    int warp = t >> 5, lane = t & 31;

    // ||k||^2 once per warp (from smem)
    float k2 = 0.f;
#pragma unroll
    for (int u = 0; u < 8; u++) {
        float4 kk = sk[lane + 32 * u];
        k2 += dot4(kk, kk);
    }
    k2 = warp_sum(k2);
    float beta = g_dim5[0];

    int row0 = blockIdx.x * 32 + warp * 4;
#pragma unroll
    for (int r = 0; r < 4; r++) {
        int row = row0 + r;
        const float4* m4 = reinterpret_cast<const float4*>(mem + (size_t)row * D);
        float d1 = 0.f, d2 = 0.f;
#pragma unroll
        for (int c = 0; c < 2; c++) {
            float4 mv[4];
#pragma unroll
            for (int u = 0; u < 4; u++) mv[u] = m4[lane + 32 * (4 * c + u)];
#pragma unroll
            for (int u = 0; u < 4; u++) {
                float4 kk = sk[lane + 32 * (4 * c + u)];
                d1 += dot4(mv[u], kk);
                d2 += dot4(mv[u], mv[u]);
            }
        }
        const float4* w4 = reinterpret_cast<const float4*>(Wg + (size_t)row * H);
        float d3 = 0.f;
#pragma unroll
        for (int c = 0; c < 4; c++) {
            float4 wv[4];
#pragma unroll
            for (int u = 0; u < 4; u++) wv[u] = w4[lane + 32 * (4 * c + u)];
#pragma unroll
            for (int u = 0; u < 4; u++) {
                float4 xv = sh[lane + 32 * (4 * c + u)];
                d3 += dot4(wv[u], xv);
            }
        }
        d1 = warp_sum(d1); d2 = warp_sum(d2); d3 = warp_sum(d3);
        if (lane == 0) {
            float sim = d1 / (sqrtf(d2) * sqrtf(k2) + EPSV);
            g_s[row] = expf(beta * sim);       // bounded: |beta*sim| small
            g_gate[row] = 1.f / (1.f + expf(-(d3 + bg[row])));
        }
    }
}

// ---------------------------------------------------------------------------
// Shift conv + pow. Each of 64 blocks reduces the full softmax denominator
// (L2-resident, deterministic), then computes w_tilde^gamma for its 256
// indices; writes g_wp and a per-block pow-sum partial. <<<64, 256>>>
// ---------------------------------------------------------------------------
__device__ __forceinline__ float wg_at(int j, float inv_sum,
                                       const float* __restrict__ lw) {
    j &= (N - 1);
    float g = g_gate[j];
    return g * g_s[j] * inv_sum + (1.f - g) * lw[j];
}

__global__ void k_shift(const float* __restrict__ lw) {
    int t = threadIdx.x;
    __shared__ float red[8];
    __shared__ float bcast;

    float s = 0.f;
#pragma unroll 8
    for (int j = t; j < N; j += 256) s += g_s[j];
    s = warp_sum(s);
    if ((t & 31) == 0) red[t >> 5] = s;
    __syncthreads();
    if (t == 0) {
        float v = 0.f;
#pragma unroll
        for (int i = 0; i < 8; i++) v += red[i];
        bcast = 1.f / v;
    }
    __syncthreads();
    float inv_sum = bcast;

    float a0 = g_dim5[2], a1 = g_dim5[3], a2 = g_dim5[4];
    float mm = fmaxf(a0, fmaxf(a1, a2));
    float e0 = expf(a0 - mm), e1 = expf(a1 - mm), e2 = expf(a2 - mm);
    float inv3 = 1.f / (e0 + e1 + e2);
    float sh0 = e0 * inv3, sh1 = e1 * inv3, sh2 = e2 * inv3;
    float gamma = g_dim5[1];

    int i = blockIdx.x * 256 + t;
    float wt = sh0 * wg_at(i - 1, inv_sum, lw)
             + sh1 * wg_at(i,     inv_sum, lw)
             + sh2 * wg_at(i + 1, inv_sum, lw);
    float wp = powf(wt, gamma);
    g_wp[i] = wp;

    __syncthreads();
    float p = warp_sum(wp);
    if ((t & 31) == 0) red[t >> 5] = p;
    __syncthreads();
    if (t == 0) {
        float v = 0.f;
#pragma unroll
        for (int i2 = 0; i2 < 8; i2++) v += red[i2];
        g_pp[blockIdx.x] = v;                 // deterministic partial
    }
}

// ---------------------------------------------------------------------------
// new_memory + weight output + memory_read PARTIALS (no atomics).
// 512 blocks x 256 threads; block handles 32 rows; thread owns 1 float4 col.
// All w values preloaded to smem; m loads batched 8 rows deep.
// <<<UB, 256>>>
// ---------------------------------------------------------------------------
__global__ void __launch_bounds__(256) k_update(const float* __restrict__ mem,
                                                float* __restrict__ out) {
    int t = threadIdx.x;                       // 0..255 -> cols 4t..4t+3
    __shared__ float red2[2];
    __shared__ float w_s[RPB];
    // reduce 64 pow-sum partials -> inv
    float v = (t < 64) ? g_pp[t] : 0.f;
    v = warp_sum(v);
    if ((t & 31) == 0 && t < 64) red2[t >> 5] = v;
    __syncthreads();
    if (t == 0) red2[0] = 1.f / (red2[0] + red2[1]);
    __syncthreads();
    float inv = red2[0];

    int base = blockIdx.x * RPB;
    if (t < RPB) {
        float wv = g_wp[base + t] * inv;
        w_s[t] = wv;
        out[D + base + t] = wv;                // weight output
    }
    __syncthreads();

    float4* newm = reinterpret_cast<float4*>(out + D + N);
    const float4* m4 = reinterpret_cast<const float4*>(mem);
    float4 e4 = reinterpret_cast<const float4*>(g_erase)[t];
    float4 a4 = reinterpret_cast<const float4*>(g_add)[t];
    float4 acc = make_float4(0.f, 0.f, 0.f, 0.f);

#pragma unroll
    for (int r0 = 0; r0 < RPB; r0 += 8) {
        float4 m[8];
#pragma unroll
        for (int u = 0; u < 8; u++)
            m[u] = m4[(size_t)(base + r0 + u) * 256 + t];
#pragma unroll
        for (int u = 0; u < 8; u++) {
            float w = w_s[r0 + u];
            acc.x += w * m[u].x; acc.y += w * m[u].y;
            acc.z += w * m[u].z; acc.w += w * m[u].w;
            float4 nm;
            nm.x = m[u].x * (1.f - w * e4.x) + w * a4.x;
            nm.y = m[u].y * (1.f - w * e4.y) + w * a4.y;
            nm.z = m[u].z * (1.f - w * e4.z) + w * a4.z;
            nm.w = m[u].w * (1.f - w * e4.w) + w * a4.w;
            newm[(size_t)(base + r0 + u) * 256 + t] = nm;
        }
    }
    reinterpret_cast<float4*>(g_part + (size_t)blockIdx.x * D)[t] = acc;
}

// ---------------------------------------------------------------------------
// Fold UB partials per column into memory_read. <<<D/128, 128>>>
// ---------------------------------------------------------------------------
__global__ void k_read(float* __restrict__ out) {
    int col = blockIdx.x * 128 + threadIdx.x;
    float s = 0.f;
#pragma unroll 8
    for (int b = 0; b < UB; b++) s += g_part[(size_t)b * D + col];
    out[col] = s;
}

// ---------------------------------------------------------------------------
extern "C" void kernel_launch(void* const* d_in, const int* in_sizes, int n_in,
                              void* d_out, int out_size) {
    const float* hidden = (const float*)d_in[0];
    const float* lw     = (const float*)d_in[1];
    const float* mem    = (const float*)d_in[2];
    const float* Wd     = (const float*)d_in[3];
    const float* bd     = (const float*)d_in[4];
    const float* Wg     = (const float*)d_in[5];
    const float* bg     = (const float*)d_in[6];
    float* out = (float*)d_out;

    k_dim   <<<DIMSZ, 256>>>(Wd, hidden, bd);
    k_row   <<<RB, 256>>>(mem, Wg, hidden, bg);
    k_shift <<<64, 256>>>(lw);
    k_update<<<UB, 256>>>(mem, out);
    k_read  <<<D / 128, 128>>>(out);
}

// round 7
// speedup vs baseline: 1.2652x; 1.2037x over previous
#include <cuda_runtime.h>
#include <math.h>

#define H 2048
#define N 16384
#define D 1024
#define EPSV 1e-8f
#define DIMSZ (5 + 3*D)   // 3077
#define UB 512            // k_update blocks
#define RPB (N / UB)      // 32 rows per update block
#define RB (N / 8)        // k_row blocks: 8 warps x 1 row = 2048 blocks

// ---- scratch (__device__ globals; no allocs allowed) ----
__device__ float g_dim5[5];          // beta, gamma, shift logits
__device__ float g_k[D];
__device__ float g_erase[D];
__device__ float g_add[D];
__device__ float g_s[N];             // exp(beta*sim)  (no max-sub; bounded)
__device__ float g_gate[N];
__device__ float g_wp[N];            // unnormalized w_tilde^gamma
__device__ float g_pp[64];           // per-block pow-sum partials
__device__ float g_part[UB * D];     // per-block memory_read partials (2 MB)

__device__ __forceinline__ float warp_sum(float v) {
#pragma unroll
    for (int o = 16; o; o >>= 1) v += __shfl_xor_sync(0xffffffffu, v, o);
    return v;
}
__device__ __forceinline__ float dot4(float4 a, float4 b) {
    return a.x * b.x + a.y * b.y + a.z * b.z + a.w * b.w;
}

// ---------------------------------------------------------------------------
// dim_out = W_dim @ hidden + b_dim, scattered into g_dim5/g_k/g_erase/g_add.
// <<<DIMSZ, 256>>>
// ---------------------------------------------------------------------------
__global__ void k_dim(const float* __restrict__ W, const float* __restrict__ h,
                      const float* __restrict__ b) {
    int row = blockIdx.x;
    const float4* w4 = reinterpret_cast<const float4*>(W + (size_t)row * H);
    const float4* h4 = reinterpret_cast<const float4*>(h);
    float s = 0.f;
#pragma unroll 2
    for (int j = threadIdx.x; j < H / 4; j += 256) {
        float4 w = w4[j], x = h4[j];
        s += dot4(w, x);
    }
    __shared__ float red[8];
    s = warp_sum(s);
    if ((threadIdx.x & 31) == 0) red[threadIdx.x >> 5] = s;
    __syncthreads();
    if (threadIdx.x == 0) {
        float v = 0.f;
#pragma unroll
        for (int i = 0; i < 8; i++) v += red[i];
        v += b[row];
        if (row < 5)              g_dim5[row] = v;
        else if (row < 5 + D)     g_k[row - 5] = v;
        else if (row < 5 + 2*D)   g_erase[row - 5 - D] = v;
        else                      g_add[row - 5 - 2*D] = v;
    }
}

// ---------------------------------------------------------------------------
// Fused heavy pass v4: k and h staged in SMEM once per block (cuts redundant
// L2 traffic ~8x vs block-per-row); ONE ROW PER WARP (8 rows/block, 2048
// blocks) to keep TLP high; loads chunked 4-deep (bounded registers).
// <<<RB, 256>>>
// ---------------------------------------------------------------------------
__global__ void __launch_bounds__(256) k_row(const float* __restrict__ mem,
                                             const float* __restrict__ Wg,
                                             const float* __restrict__ h,
                                             const float* __restrict__ bg) {
    __shared__ float4 sk[D / 4];     // 4 KB
    __shared__ float4 sh[H / 4];     // 8 KB
    int t = threadIdx.x;
    sk[t] = reinterpret_cast<const float4*>(g_k)[t];
    {
        const float4* h4 = reinterpret_cast<const float4*>(h);
        sh[t] = h4[t];
        sh[t + 256] = h4[t + 256];
    }
    __syncthreads();

    int warp = t >> 5, lane = t & 31;
    int row = blockIdx.x * 8 + warp;

    // ||k||^2 per warp (from smem; cheap)
    float k2 = 0.f;
#pragma unroll
    for (int u = 0; u < 8; u++) {
        float4 kk = sk[lane + 32 * u];
        k2 += dot4(kk, kk);
    }

    const float4* m4 = reinterpret_cast<const float4*>(mem + (size_t)row * D);
    float d1 = 0.f, d2 = 0.f;
#pragma unroll
    for (int c = 0; c < 2; c++) {
        float4 mv[4];
#pragma unroll
        for (int u = 0; u < 4; u++) mv[u] = m4[lane + 32 * (4 * c + u)];
#pragma unroll
        for (int u = 0; u < 4; u++) {
            float4 kk = sk[lane + 32 * (4 * c + u)];
            d1 += dot4(mv[u], kk);
            d2 += dot4(mv[u], mv[u]);
        }
    }
    const float4* w4 = reinterpret_cast<const float4*>(Wg + (size_t)row * H);
    float d3 = 0.f;
#pragma unroll
    for (int c = 0; c < 4; c++) {
        float4 wv[4];
#pragma unroll
        for (int u = 0; u < 4; u++) wv[u] = w4[lane + 32 * (4 * c + u)];
#pragma unroll
        for (int u = 0; u < 4; u++) {
            float4 xv = sh[lane + 32 * (4 * c + u)];
            d3 += dot4(wv[u], xv);
        }
    }
    d1 = warp_sum(d1); d2 = warp_sum(d2); d3 = warp_sum(d3); k2 = warp_sum(k2);
    if (lane == 0) {
        float sim = d1 / (sqrtf(d2) * sqrtf(k2) + EPSV);
        g_s[row] = expf(g_dim5[0] * sim);      // bounded: |beta*sim| small
        g_gate[row] = 1.f / (1.f + expf(-(d3 + bg[row])));
    }
}

// ---------------------------------------------------------------------------
// Shift conv + pow. Each of 64 blocks reduces the full softmax denominator
// (L2-resident, deterministic), then computes w_tilde^gamma for its 256
// indices; writes g_wp and a per-block pow-sum partial. <<<64, 256>>>
// ---------------------------------------------------------------------------
__device__ __forceinline__ float wg_at(int j, float inv_sum,
                                       const float* __restrict__ lw) {
    j &= (N - 1);
    float g = g_gate[j];
    return g * g_s[j] * inv_sum + (1.f - g) * lw[j];
}

__global__ void k_shift(const float* __restrict__ lw) {
    int t = threadIdx.x;
    __shared__ float red[8];
    __shared__ float bcast;

    float s = 0.f;
#pragma unroll 8
    for (int j = t; j < N; j += 256) s += g_s[j];
    s = warp_sum(s);
    if ((t & 31) == 0) red[t >> 5] = s;
    __syncthreads();
    if (t == 0) {
        float v = 0.f;
#pragma unroll
        for (int i = 0; i < 8; i++) v += red[i];
        bcast = 1.f / v;
    }
    __syncthreads();
    float inv_sum = bcast;

    float a0 = g_dim5[2], a1 = g_dim5[3], a2 = g_dim5[4];
    float mm = fmaxf(a0, fmaxf(a1, a2));
    float e0 = expf(a0 - mm), e1 = expf(a1 - mm), e2 = expf(a2 - mm);
    float inv3 = 1.f / (e0 + e1 + e2);
    float sh0 = e0 * inv3, sh1 = e1 * inv3, sh2 = e2 * inv3;
    float gamma = g_dim5[1];

    int i = blockIdx.x * 256 + t;
    float wt = sh0 * wg_at(i - 1, inv_sum, lw)
             + sh1 * wg_at(i,     inv_sum, lw)
             + sh2 * wg_at(i + 1, inv_sum, lw);
    float wp = powf(wt, gamma);
    g_wp[i] = wp;

    __syncthreads();
    float p = warp_sum(wp);
    if ((t & 31) == 0) red[t >> 5] = p;
    __syncthreads();
    if (t == 0) {
        float v = 0.f;
#pragma unroll
        for (int i2 = 0; i2 < 8; i2++) v += red[i2];
        g_pp[blockIdx.x] = v;                 // deterministic partial
    }
}

// ---------------------------------------------------------------------------
// new_memory + weight output + memory_read PARTIALS (no atomics).
// 512 blocks x 256 threads; block handles 32 rows; thread owns 1 float4 col.
// All w values preloaded to smem; m loads batched 8 rows deep.
// <<<UB, 256>>>
// ---------------------------------------------------------------------------
__global__ void __launch_bounds__(256) k_update(const float* __restrict__ mem,
                                                float* __restrict__ out) {
    int t = threadIdx.x;                       // 0..255 -> cols 4t..4t+3
    __shared__ float red2[2];
    __shared__ float w_s[RPB];
    // reduce 64 pow-sum partials -> inv
    float v = (t < 64) ? g_pp[t] : 0.f;
    v = warp_sum(v);
    if ((t & 31) == 0 && t < 64) red2[t >> 5] = v;
    __syncthreads();
    if (t == 0) red2[0] = 1.f / (red2[0] + red2[1]);
    __syncthreads();
    float inv = red2[0];

    int base = blockIdx.x * RPB;
    if (t < RPB) {
        float wv = g_wp[base + t] * inv;
        w_s[t] = wv;
        out[D + base + t] = wv;                // weight output
    }
    __syncthreads();

    float4* newm = reinterpret_cast<float4*>(out + D + N);
    const float4* m4 = reinterpret_cast<const float4*>(mem);
    float4 e4 = reinterpret_cast<const float4*>(g_erase)[t];
    float4 a4 = reinterpret_cast<const float4*>(g_add)[t];
    float4 acc = make_float4(0.f, 0.f, 0.f, 0.f);

#pragma unroll
    for (int r0 = 0; r0 < RPB; r0 += 8) {
        float4 m[8];
#pragma unroll
        for (int u = 0; u < 8; u++)
            m[u] = m4[(size_t)(base + r0 + u) * 256 + t];
#pragma unroll
        for (int u = 0; u < 8; u++) {
            float w = w_s[r0 + u];
            acc.x += w * m[u].x; acc.y += w * m[u].y;
            acc.z += w * m[u].z; acc.w += w * m[u].w;
            float4 nm;
            nm.x = m[u].x * (1.f - w * e4.x) + w * a4.x;
            nm.y = m[u].y * (1.f - w * e4.y) + w * a4.y;
            nm.z = m[u].z * (1.f - w * e4.z) + w * a4.z;
            nm.w = m[u].w * (1.f - w * e4.w) + w * a4.w;
            newm[(size_t)(base + r0 + u) * 256 + t] = nm;
        }
    }
    reinterpret_cast<float4*>(g_part + (size_t)blockIdx.x * D)[t] = acc;
}

// ---------------------------------------------------------------------------
// Fold UB partials per column into memory_read. <<<D/128, 128>>>
// ---------------------------------------------------------------------------
__global__ void k_read(float* __restrict__ out) {
    int col = blockIdx.x * 128 + threadIdx.x;
    float s = 0.f;
#pragma unroll 8
    for (int b = 0; b < UB; b++) s += g_part[(size_t)b * D + col];
    out[col] = s;
}

// ---------------------------------------------------------------------------
extern "C" void kernel_launch(void* const* d_in, const int* in_sizes, int n_in,
                              void* d_out, int out_size) {
    const float* hidden = (const float*)d_in[0];
    const float* lw     = (const float*)d_in[1];
    const float* mem    = (const float*)d_in[2];
    const float* Wd     = (const float*)d_in[3];
    const float* bd     = (const float*)d_in[4];
    const float* Wg     = (const float*)d_in[5];
    const float* bg     = (const float*)d_in[6];
    float* out = (float*)d_out;

    k_dim   <<<DIMSZ, 256>>>(Wd, hidden, bd);
    k_row   <<<RB, 256>>>(mem, Wg, hidden, bg);
    k_shift <<<64, 256>>>(lw);
    k_update<<<UB, 256>>>(mem, out);
    k_read  <<<D / 128, 128>>>(out);
}

// round 8
// speedup vs baseline: 1.3186x; 1.0422x over previous
#include <cuda_runtime.h>
#include <math.h>

#define H 2048
#define N 16384
#define D 1024
#define EPSV 1e-8f
#define DIMSZ (5 + 3*D)   // 3077
#define UB 512            // k_update blocks
#define RPB (N / UB)      // 32 rows per update block
#define RB (N / 8)        // k_row blocks: 8 warps x 1 row = 2048 blocks

// ---- scratch (__device__ globals; no allocs allowed) ----
__device__ float g_dim5[5];          // beta, gamma, shift logits
__device__ float g_k[D];
__device__ float g_erase[D];
__device__ float g_add[D];
__device__ float g_s[N];             // exp(beta*sim)  (no max-sub; bounded)
__device__ float g_gate[N];
__device__ float g_wp[N];            // unnormalized w_tilde^gamma
__device__ float g_pp[64];           // per-block pow-sum partials
__device__ float g_part[UB * D];     // per-block memory_read partials (2 MB)

__device__ __forceinline__ float warp_sum(float v) {
#pragma unroll
    for (int o = 16; o; o >>= 1) v += __shfl_xor_sync(0xffffffffu, v, o);
    return v;
}
__device__ __forceinline__ float dot4(float4 a, float4 b) {
    return a.x * b.x + a.y * b.y + a.z * b.z + a.w * b.w;
}

// ---------------------------------------------------------------------------
// dim_out = W_dim @ hidden + b_dim, scattered into g_dim5/g_k/g_erase/g_add.
// W_dim is single-use: stream it (evict-first) to protect L2 for `memory`.
// <<<DIMSZ, 256>>>
// ---------------------------------------------------------------------------
__global__ void k_dim(const float* __restrict__ W, const float* __restrict__ h,
                      const float* __restrict__ b) {
    int row = blockIdx.x;
    const float4* w4 = reinterpret_cast<const float4*>(W + (size_t)row * H);
    const float4* h4 = reinterpret_cast<const float4*>(h);
    float s = 0.f;
#pragma unroll 2
    for (int j = threadIdx.x; j < H / 4; j += 256) {
        float4 w = __ldcs(w4 + j);
        float4 x = h4[j];
        s += dot4(w, x);
    }
    __shared__ float red[8];
    s = warp_sum(s);
    if ((threadIdx.x & 31) == 0) red[threadIdx.x >> 5] = s;
    __syncthreads();
    if (threadIdx.x == 0) {
        float v = 0.f;
#pragma unroll
        for (int i = 0; i < 8; i++) v += red[i];
        v += b[row];
        if (row < 5)              g_dim5[row] = v;
        else if (row < 5 + D)     g_k[row - 5] = v;
        else if (row < 5 + 2*D)   g_erase[row - 5 - D] = v;
        else                      g_add[row - 5 - 2*D] = v;
    }
}

// ---------------------------------------------------------------------------
// Fused heavy pass v5: k and h staged in SMEM once per block; ONE ROW PER
// WARP (2048 blocks). mem reads cached normally (want L2 retention for
// k_update); Wg streamed evict-first, 8-deep batched (2/3 of the traffic).
// <<<RB, 256>>>
// ---------------------------------------------------------------------------
__global__ void __launch_bounds__(256) k_row(const float* __restrict__ mem,
                                             const float* __restrict__ Wg,
                                             const float* __restrict__ h,
                                             const float* __restrict__ bg) {
    __shared__ float4 sk[D / 4];     // 4 KB
    __shared__ float4 sh[H / 4];     // 8 KB
    int t = threadIdx.x;
    sk[t] = reinterpret_cast<const float4*>(g_k)[t];
    {
        const float4* h4 = reinterpret_cast<const float4*>(h);
        sh[t] = h4[t];
        sh[t + 256] = h4[t + 256];
    }
    __syncthreads();

    int warp = t >> 5, lane = t & 31;
    int row = blockIdx.x * 8 + warp;

    // ||k||^2 per warp (from smem; cheap)
    float k2 = 0.f;
#pragma unroll
    for (int u = 0; u < 8; u++) {
        float4 kk = sk[lane + 32 * u];
        k2 += dot4(kk, kk);
    }

    const float4* m4 = reinterpret_cast<const float4*>(mem + (size_t)row * D);
    float d1 = 0.f, d2 = 0.f;
#pragma unroll
    for (int c = 0; c < 2; c++) {
        float4 mv[4];
#pragma unroll
        for (int u = 0; u < 4; u++) mv[u] = m4[lane + 32 * (4 * c + u)];
#pragma unroll
        for (int u = 0; u < 4; u++) {
            float4 kk = sk[lane + 32 * (4 * c + u)];
            d1 += dot4(mv[u], kk);
            d2 += dot4(mv[u], mv[u]);
        }
    }
    // gate GEMV: Wg streamed evict-first, 8-deep batches (mv regs retired)
    const float4* w4 = reinterpret_cast<const float4*>(Wg + (size_t)row * H);
    float d3 = 0.f;
#pragma unroll
    for (int c = 0; c < 2; c++) {
        float4 wv[8];
#pragma unroll
        for (int u = 0; u < 8; u++) wv[u] = __ldcs(w4 + lane + 32 * (8 * c + u));
#pragma unroll
        for (int u = 0; u < 8; u++) {
            float4 xv = sh[lane + 32 * (8 * c + u)];
            d3 += dot4(wv[u], xv);
        }
    }
    d1 = warp_sum(d1); d2 = warp_sum(d2); d3 = warp_sum(d3); k2 = warp_sum(k2);
    if (lane == 0) {
        float sim = d1 / (sqrtf(d2) * sqrtf(k2) + EPSV);
        g_s[row] = expf(g_dim5[0] * sim);      // bounded: |beta*sim| small
        g_gate[row] = 1.f / (1.f + expf(-(d3 + bg[row])));
    }
}

// ---------------------------------------------------------------------------
// Shift conv + pow. Each of 64 blocks reduces the full softmax denominator
// (L2-resident, deterministic), then computes w_tilde^gamma for its 256
// indices; writes g_wp and a per-block pow-sum partial. <<<64, 256>>>
// ---------------------------------------------------------------------------
__device__ __forceinline__ float wg_at(int j, float inv_sum,
                                       const float* __restrict__ lw) {
    j &= (N - 1);
    float g = g_gate[j];
    return g * g_s[j] * inv_sum + (1.f - g) * lw[j];
}

__global__ void k_shift(const float* __restrict__ lw) {
    int t = threadIdx.x;
    __shared__ float red[8];
    __shared__ float bcast;

    float s = 0.f;
#pragma unroll 8
    for (int j = t; j < N; j += 256) s += g_s[j];
    s = warp_sum(s);
    if ((t & 31) == 0) red[t >> 5] = s;
    __syncthreads();
    if (t == 0) {
        float v = 0.f;
#pragma unroll
        for (int i = 0; i < 8; i++) v += red[i];
        bcast = 1.f / v;
    }
    __syncthreads();
    float inv_sum = bcast;

    float a0 = g_dim5[2], a1 = g_dim5[3], a2 = g_dim5[4];
    float mm = fmaxf(a0, fmaxf(a1, a2));
    float e0 = expf(a0 - mm), e1 = expf(a1 - mm), e2 = expf(a2 - mm);
    float inv3 = 1.f / (e0 + e1 + e2);
    float sh0 = e0 * inv3, sh1 = e1 * inv3, sh2 = e2 * inv3;
    float gamma = g_dim5[1];

    int i = blockIdx.x * 256 + t;
    float wt = sh0 * wg_at(i - 1, inv_sum, lw)
             + sh1 * wg_at(i,     inv_sum, lw)
             + sh2 * wg_at(i + 1, inv_sum, lw);
    float wp = powf(wt, gamma);
    g_wp[i] = wp;

    __syncthreads();
    float p = warp_sum(wp);
    if ((t & 31) == 0) red[t >> 5] = p;
    __syncthreads();
    if (t == 0) {
        float v = 0.f;
#pragma unroll
        for (int i2 = 0; i2 < 8; i2++) v += red[i2];
        g_pp[blockIdx.x] = v;                 // deterministic partial
    }
}

// ---------------------------------------------------------------------------
// new_memory + weight output + memory_read PARTIALS (no atomics).
// 512 blocks x 256 threads; block handles 32 rows; thread owns 1 float4 col.
// mem reads should now largely hit L2 (kept resident by k_row's streaming
// hints). <<<UB, 256>>>
// ---------------------------------------------------------------------------
__global__ void __launch_bounds__(256) k_update(const float* __restrict__ mem,
                                                float* __restrict__ out) {
    int t = threadIdx.x;                       // 0..255 -> cols 4t..4t+3
    __shared__ float red2[2];
    __shared__ float w_s[RPB];
    // reduce 64 pow-sum partials -> inv
    float v = (t < 64) ? g_pp[t] : 0.f;
    v = warp_sum(v);
    if ((t & 31) == 0 && t < 64) red2[t >> 5] = v;
    __syncthreads();
    if (t == 0) red2[0] = 1.f / (red2[0] + red2[1]);
    __syncthreads();
    float inv = red2[0];

    int base = blockIdx.x * RPB;
    if (t < RPB) {
        float wv = g_wp[base + t] * inv;
        w_s[t] = wv;
        out[D + base + t] = wv;                // weight output
    }
    __syncthreads();

    float4* newm = reinterpret_cast<float4*>(out + D + N);
    const float4* m4 = reinterpret_cast<const float4*>(mem);
    float4 e4 = reinterpret_cast<const float4*>(g_erase)[t];
    float4 a4 = reinterpret_cast<const float4*>(g_add)[t];
    float4 acc = make_float4(0.f, 0.f, 0.f, 0.f);

#pragma unroll
    for (int r0 = 0; r0 < RPB; r0 += 8) {
        float4 m[8];
#pragma unroll
        for (int u = 0; u < 8; u++)
            m[u] = m4[(size_t)(base + r0 + u) * 256 + t];
#pragma unroll
        for (int u = 0; u < 8; u++) {
            float w = w_s[r0 + u];
            acc.x += w * m[u].x; acc.y += w * m[u].y;
            acc.z += w * m[u].z; acc.w += w * m[u].w;
            float4 nm;
            nm.x = m[u].x * (1.f - w * e4.x) + w * a4.x;
            nm.y = m[u].y * (1.f - w * e4.y) + w * a4.y;
            nm.z = m[u].z * (1.f - w * e4.z) + w * a4.z;
            nm.w = m[u].w * (1.f - w * e4.w) + w * a4.w;
            newm[(size_t)(base + r0 + u) * 256 + t] = nm;
        }
    }
    reinterpret_cast<float4*>(g_part + (size_t)blockIdx.x * D)[t] = acc;
}

// ---------------------------------------------------------------------------
// Fold UB partials per column into memory_read. <<<D/128, 128>>>
// ---------------------------------------------------------------------------
__global__ void k_read(float* __restrict__ out) {
    int col = blockIdx.x * 128 + threadIdx.x;
    float s = 0.f;
#pragma unroll 8
    for (int b = 0; b < UB; b++) s += g_part[(size_t)b * D + col];
    out[col] = s;
}

// ---------------------------------------------------------------------------
extern "C" void kernel_launch(void* const* d_in, const int* in_sizes, int n_in,
                              void* d_out, int out_size) {
    const float* hidden = (const float*)d_in[0];
    const float* lw     = (const float*)d_in[1];
    const float* mem    = (const float*)d_in[2];
    const float* Wd     = (const float*)d_in[3];
    const float* bd     = (const float*)d_in[4];
    const float* Wg     = (const float*)d_in[5];
    const float* bg     = (const float*)d_in[6];
    float* out = (float*)d_out;

    k_dim   <<<DIMSZ, 256>>>(Wd, hidden, bd);
    k_row   <<<RB, 256>>>(mem, Wg, hidden, bg);
    k_shift <<<64, 256>>>(lw);
    k_update<<<UB, 256>>>(mem, out);
    k_read  <<<D / 128, 128>>>(out);
}

// round 9
// speedup vs baseline: 1.3738x; 1.0419x over previous
#include <cuda_runtime.h>
#include <math.h>

#define H 2048
#define N 16384
#define D 1024
#define EPSV 1e-8f
#define DIMSZ (5 + 3*D)   // 3077
#define UB 512            // fused shift+update blocks
#define RPB (N / UB)      // 32 rows per fused block
#define RB (N / 8)        // k_row blocks: 8 warps x 1 row = 2048 blocks

// ---- scratch (__device__ globals; no allocs allowed) ----
__device__ float g_dim5[5];          // beta, gamma, shift logits
__device__ float g_k[D];
__device__ float g_erase[D];
__device__ float g_add[D];
__device__ float g_s[N];             // exp(beta*sim)  (no max-sub; bounded)
__device__ float g_gate[N];
__device__ float g_sp[RB];           // per-k_row-block exp partial sums
__device__ float g_pp[UB];           // per-fused-block pow-sum partials
__device__ float g_part[UB * D];     // per-block memory_read partials (2 MB)
__device__ unsigned g_arrive;        // monotonic grid-barrier ticket counter

__device__ __forceinline__ float warp_sum(float v) {
#pragma unroll
    for (int o = 16; o; o >>= 1) v += __shfl_xor_sync(0xffffffffu, v, o);
    return v;
}
__device__ __forceinline__ float dot4(float4 a, float4 b) {
    return a.x * b.x + a.y * b.y + a.z * b.z + a.w * b.w;
}

// ---------------------------------------------------------------------------
// dim_out = W_dim @ hidden + b_dim, scattered into g_dim5/g_k/g_erase/g_add.
// <<<DIMSZ, 256>>>
// ---------------------------------------------------------------------------
__global__ void k_dim(const float* __restrict__ W, const float* __restrict__ h,
                      const float* __restrict__ b) {
    int row = blockIdx.x;
    const float4* w4 = reinterpret_cast<const float4*>(W + (size_t)row * H);
    const float4* h4 = reinterpret_cast<const float4*>(h);
    float s = 0.f;
#pragma unroll 2
    for (int j = threadIdx.x; j < H / 4; j += 256) {
        float4 w = __ldcs(w4 + j);
        float4 x = h4[j];
        s += dot4(w, x);
    }
    __shared__ float red[8];
    s = warp_sum(s);
    if ((threadIdx.x & 31) == 0) red[threadIdx.x >> 5] = s;
    __syncthreads();
    if (threadIdx.x == 0) {
        float v = 0.f;
#pragma unroll
        for (int i = 0; i < 8; i++) v += red[i];
        v += b[row];
        if (row < 5)              g_dim5[row] = v;
        else if (row < 5 + D)     g_k[row - 5] = v;
        else if (row < 5 + 2*D)   g_erase[row - 5 - D] = v;
        else                      g_add[row - 5 - 2*D] = v;
    }
}

// ---------------------------------------------------------------------------
// Fused heavy pass: k and h staged in SMEM once per block; ONE ROW PER WARP.
// Also emits per-block exp partial sums (g_sp) for the softmax denominator.
// <<<RB, 256>>>
// ---------------------------------------------------------------------------
__global__ void __launch_bounds__(256) k_row(const float* __restrict__ mem,
                                             const float* __restrict__ Wg,
                                             const float* __restrict__ h,
                                             const float* __restrict__ bg) {
    __shared__ float4 sk[D / 4];     // 4 KB
    __shared__ float4 sh[H / 4];     // 8 KB
    __shared__ float sexp[8];
    int t = threadIdx.x;
    sk[t] = reinterpret_cast<const float4*>(g_k)[t];
    {
        const float4* h4 = reinterpret_cast<const float4*>(h);
        sh[t] = h4[t];
        sh[t + 256] = h4[t + 256];
    }
    __syncthreads();

    int warp = t >> 5, lane = t & 31;
    int row = blockIdx.x * 8 + warp;

    float k2 = 0.f;
#pragma unroll
    for (int u = 0; u < 8; u++) {
        float4 kk = sk[lane + 32 * u];
        k2 += dot4(kk, kk);
    }

    const float4* m4 = reinterpret_cast<const float4*>(mem + (size_t)row * D);
    float d1 = 0.f, d2 = 0.f;
#pragma unroll
    for (int c = 0; c < 2; c++) {
        float4 mv[4];
#pragma unroll
        for (int u = 0; u < 4; u++) mv[u] = m4[lane + 32 * (4 * c + u)];
#pragma unroll
        for (int u = 0; u < 4; u++) {
            float4 kk = sk[lane + 32 * (4 * c + u)];
            d1 += dot4(mv[u], kk);
            d2 += dot4(mv[u], mv[u]);
        }
    }
    const float4* w4 = reinterpret_cast<const float4*>(Wg + (size_t)row * H);
    float d3 = 0.f;
#pragma unroll
    for (int c = 0; c < 2; c++) {
        float4 wv[8];
#pragma unroll
        for (int u = 0; u < 8; u++) wv[u] = __ldcs(w4 + lane + 32 * (8 * c + u));
#pragma unroll
        for (int u = 0; u < 8; u++) {
            float4 xv = sh[lane + 32 * (8 * c + u)];
            d3 += dot4(wv[u], xv);
        }
    }
    d1 = warp_sum(d1); d2 = warp_sum(d2); d3 = warp_sum(d3); k2 = warp_sum(k2);
    if (lane == 0) {
        float sim = d1 / (sqrtf(d2) * sqrtf(k2) + EPSV);
        float ev = expf(g_dim5[0] * sim);      // bounded: |beta*sim| small
        g_s[row] = ev;
        sexp[warp] = ev;
        g_gate[row] = 1.f / (1.f + expf(-(d3 + bg[row])));
    }
    __syncthreads();
    if (t == 0) {
        float v = 0.f;
#pragma unroll
        for (int i = 0; i < 8; i++) v += sexp[i];
        g_sp[blockIdx.x] = v;                  // softmax denominator partial
    }
}

// ---------------------------------------------------------------------------
// FUSED shift + update + weight output (grid barrier between phases).
//   phase 0: reduce g_sp -> softmax inv_sum
//   phase 1: shift conv + pow for my 32 rows (t<32) -> smem + g_pp partial
//   grid sync (monotonic ticket; replay-safe, all 512 blocks co-resident)
//   phase 2: reduce g_pp -> inv; write weight; memory update + read partials
// <<<UB, 256>>>
// ---------------------------------------------------------------------------
__device__ __forceinline__ float wg_at(int j, float inv_sum,
                                       const float* __restrict__ lw) {
    j &= (N - 1);
    float g = g_gate[j];
    return g * g_s[j] * inv_sum + (1.f - g) * lw[j];
}

__global__ void __launch_bounds__(256, 4) k_fused(const float* __restrict__ mem,
                                                  const float* __restrict__ lw,
                                                  float* __restrict__ out) {
    int t = threadIdx.x;
    int warp = t >> 5, lane = t & 31;
    __shared__ float red[8];
    __shared__ float bc;
    __shared__ float w_s[RPB];

    // phase 0: softmax denominator from 2048 partials
    float s = 0.f;
#pragma unroll
    for (int u = 0; u < RB / 256; u++) s += g_sp[t + 256 * u];
    s = warp_sum(s);
    if (lane == 0) red[warp] = s;
    __syncthreads();
    if (t == 0) {
        float v = 0.f;
#pragma unroll
        for (int i = 0; i < 8; i++) v += red[i];
        bc = 1.f / v;
    }
    __syncthreads();
    float inv_sum = bc;

    // phase 1: shift conv + pow for this block's 32 rows (warp 0 only)
    int base = blockIdx.x * RPB;
    if (t < RPB) {
        float a0 = g_dim5[2], a1 = g_dim5[3], a2 = g_dim5[4];
        float mm = fmaxf(a0, fmaxf(a1, a2));
        float e0 = expf(a0 - mm), e1 = expf(a1 - mm), e2 = expf(a2 - mm);
        float inv3 = 1.f / (e0 + e1 + e2);
        float gamma = g_dim5[1];
        int i = base + t;
        float wt = e0 * inv3 * wg_at(i - 1, inv_sum, lw)
                 + e1 * inv3 * wg_at(i,     inv_sum, lw)
                 + e2 * inv3 * wg_at(i + 1, inv_sum, lw);
        float wp = powf(wt, gamma);
        w_s[t] = wp;
        float p = warp_sum(wp);
        if (t == 0) g_pp[blockIdx.x] = p;     // pow-sum partial
    }
    __syncthreads();

    // grid sync: monotonic ticket counter (exactly UB arrivals per launch)
    if (t == 0) {
        __threadfence();
        unsigned ticket = atomicAdd(&g_arrive, 1u);
        unsigned target = (ticket / UB + 1u) * UB;
        while (atomicAdd(&g_arrive, 0u) < target) { }
    }
    __syncthreads();
    __threadfence();

    // phase 2: global pow-sum -> inv; weight out; memory update
    float v2 = g_pp[t] + g_pp[t + 256];
    v2 = warp_sum(v2);
    if (lane == 0) red[warp] = v2;
    __syncthreads();
    if (t == 0) {
        float v = 0.f;
#pragma unroll
        for (int i = 0; i < 8; i++) v += red[i];
        bc = 1.f / v;
    }
    __syncthreads();
    float inv = bc;

    if (t < RPB) out[D + base + t] = w_s[t] * inv;   // weight output

    float4* newm = reinterpret_cast<float4*>(out + D + N);
    const float4* m4 = reinterpret_cast<const float4*>(mem);
    float4 e4 = reinterpret_cast<const float4*>(g_erase)[t];
    float4 a4 = reinterpret_cast<const float4*>(g_add)[t];
    float4 acc = make_float4(0.f, 0.f, 0.f, 0.f);

#pragma unroll
    for (int r0 = 0; r0 < RPB; r0 += 8) {
        float4 m[8];
#pragma unroll
        for (int u = 0; u < 8; u++)
            m[u] = m4[(size_t)(base + r0 + u) * 256 + t];
#pragma unroll
        for (int u = 0; u < 8; u++) {
            float w = w_s[r0 + u] * inv;
            acc.x += w * m[u].x; acc.y += w * m[u].y;
            acc.z += w * m[u].z; acc.w += w * m[u].w;
            float4 nm;
            nm.x = m[u].x * (1.f - w * e4.x) + w * a4.x;
            nm.y = m[u].y * (1.f - w * e4.y) + w * a4.y;
            nm.z = m[u].z * (1.f - w * e4.z) + w * a4.z;
            nm.w = m[u].w * (1.f - w * e4.w) + w * a4.w;
            newm[(size_t)(base + r0 + u) * 256 + t] = nm;
        }
    }
    reinterpret_cast<float4*>(g_part + (size_t)blockIdx.x * D)[t] = acc;
}

// ---------------------------------------------------------------------------
// Fold UB partials per column into memory_read. <<<D/128, 128>>>
// ---------------------------------------------------------------------------
__global__ void k_read(float* __restrict__ out) {
    int col = blockIdx.x * 128 + threadIdx.x;
    float s = 0.f;
#pragma unroll 8
    for (int b = 0; b < UB; b++) s += g_part[(size_t)b * D + col];
    out[col] = s;
}

// ---------------------------------------------------------------------------
extern "C" void kernel_launch(void* const* d_in, const int* in_sizes, int n_in,
                              void* d_out, int out_size) {
    const float* hidden = (const float*)d_in[0];
    const float* lw     = (const float*)d_in[1];
    const float* mem    = (const float*)d_in[2];
    const float* Wd     = (const float*)d_in[3];
    const float* bd     = (const float*)d_in[4];
    const float* Wg     = (const float*)d_in[5];
    const float* bg     = (const float*)d_in[6];
    float* out = (float*)d_out;

    k_dim   <<<DIMSZ, 256>>>(Wd, hidden, bd);
    k_row   <<<RB, 256>>>(mem, Wg, hidden, bg);
    k_fused <<<UB, 256>>>(mem, lw, out);
    k_read  <<<D / 128, 128>>>(out);
}

// round 10
// speedup vs baseline: 1.4983x; 1.0906x over previous
#include <cuda_runtime.h>
#include <math.h>

#define H 2048
#define N 16384
#define D 1024
#define EPSV 1e-8f
#define DIMSZ (5 + 3*D)   // 3077
#define UB 512            // fused shift+update blocks
#define RPB (N / UB)      // 32 rows per fused block
#define RB (N / 8)        // k_row blocks: 8 warps x 1 row = 2048 blocks

// ---- scratch (__device__ globals; no allocs allowed) ----
__device__ float g_dim5[5];          // beta, gamma, shift logits
__device__ float g_k[D];
__device__ float g_erase[D];
__device__ float g_add[D];
__device__ float g_s[N];             // exp(beta*sim)  (no max-sub; bounded)
__device__ float g_gate[N];
__device__ float g_sp[RB];           // per-k_row-block exp partial sums
__device__ float g_pp[UB];           // per-fused-block pow-sum partials
__device__ unsigned g_arrive;        // monotonic grid-barrier ticket counter

__device__ __forceinline__ float warp_sum(float v) {
#pragma unroll
    for (int o = 16; o; o >>= 1) v += __shfl_xor_sync(0xffffffffu, v, o);
    return v;
}
__device__ __forceinline__ float dot4(float4 a, float4 b) {
    return a.x * b.x + a.y * b.y + a.z * b.z + a.w * b.w;
}

// ---------------------------------------------------------------------------
// dim_out = W_dim @ hidden + b_dim, scattered into g_dim5/g_k/g_erase/g_add.
// First D blocks also zero the memory_read region of d_out.
// <<<DIMSZ, 256>>>
// ---------------------------------------------------------------------------
__global__ void k_dim(const float* __restrict__ W, const float* __restrict__ h,
                      const float* __restrict__ b, float* __restrict__ out) {
    int row = blockIdx.x;
    if (row < D && threadIdx.x == 1) out[row] = 0.f;   // memory_read zero-init
    const float4* w4 = reinterpret_cast<const float4*>(W + (size_t)row * H);
    const float4* h4 = reinterpret_cast<const float4*>(h);
    float s = 0.f;
#pragma unroll 2
    for (int j = threadIdx.x; j < H / 4; j += 256) {
        float4 w = __ldcs(w4 + j);
        float4 x = h4[j];
        s += dot4(w, x);
    }
    __shared__ float red[8];
    s = warp_sum(s);
    if ((threadIdx.x & 31) == 0) red[threadIdx.x >> 5] = s;
    __syncthreads();
    if (threadIdx.x == 0) {
        float v = 0.f;
#pragma unroll
        for (int i = 0; i < 8; i++) v += red[i];
        v += b[row];
        if (row < 5)              g_dim5[row] = v;
        else if (row < 5 + D)     g_k[row - 5] = v;
        else if (row < 5 + 2*D)   g_erase[row - 5 - D] = v;
        else                      g_add[row - 5 - 2*D] = v;
    }
}

// ---------------------------------------------------------------------------
// Fused heavy pass: k and h staged in SMEM once per block; ONE ROW PER WARP.
// Also emits per-block exp partial sums (g_sp) for the softmax denominator.
// <<<RB, 256>>>
// ---------------------------------------------------------------------------
__global__ void __launch_bounds__(256) k_row(const float* __restrict__ mem,
                                             const float* __restrict__ Wg,
                                             const float* __restrict__ h,
                                             const float* __restrict__ bg) {
    __shared__ float4 sk[D / 4];     // 4 KB
    __shared__ float4 sh[H / 4];     // 8 KB
    __shared__ float sexp[8];
    int t = threadIdx.x;
    sk[t] = reinterpret_cast<const float4*>(g_k)[t];
    {
        const float4* h4 = reinterpret_cast<const float4*>(h);
        sh[t] = h4[t];
        sh[t + 256] = h4[t + 256];
    }
    __syncthreads();

    int warp = t >> 5, lane = t & 31;
    int row = blockIdx.x * 8 + warp;

    float k2 = 0.f;
#pragma unroll
    for (int u = 0; u < 8; u++) {
        float4 kk = sk[lane + 32 * u];
        k2 += dot4(kk, kk);
    }

    const float4* m4 = reinterpret_cast<const float4*>(mem + (size_t)row * D);
    float d1 = 0.f, d2 = 0.f;
#pragma unroll
    for (int c = 0; c < 2; c++) {
        float4 mv[4];
#pragma unroll
        for (int u = 0; u < 4; u++) mv[u] = m4[lane + 32 * (4 * c + u)];
#pragma unroll
        for (int u = 0; u < 4; u++) {
            float4 kk = sk[lane + 32 * (4 * c + u)];
            d1 += dot4(mv[u], kk);
            d2 += dot4(mv[u], mv[u]);
        }
    }
    const float4* w4 = reinterpret_cast<const float4*>(Wg + (size_t)row * H);
    float d3 = 0.f;
#pragma unroll
    for (int c = 0; c < 2; c++) {
        float4 wv[8];
#pragma unroll
        for (int u = 0; u < 8; u++) wv[u] = __ldcs(w4 + lane + 32 * (8 * c + u));
#pragma unroll
        for (int u = 0; u < 8; u++) {
            float4 xv = sh[lane + 32 * (8 * c + u)];
            d3 += dot4(wv[u], xv);
        }
    }
    d1 = warp_sum(d1); d2 = warp_sum(d2); d3 = warp_sum(d3); k2 = warp_sum(k2);
    if (lane == 0) {
        float sim = d1 / (sqrtf(d2) * sqrtf(k2) + EPSV);
        float ev = expf(g_dim5[0] * sim);      // bounded: |beta*sim| small
        g_s[row] = ev;
        sexp[warp] = ev;
        g_gate[row] = 1.f / (1.f + expf(-(d3 + bg[row])));
    }
    __syncthreads();
    if (t == 0) {
        float v = 0.f;
#pragma unroll
        for (int i = 0; i < 8; i++) v += sexp[i];
        g_sp[blockIdx.x] = v;                  // softmax denominator partial
    }
}

// ---------------------------------------------------------------------------
// FUSED shift + update + weight output + memory_read (grid barrier between
// phases; memory_read via atomicAdd into pre-zeroed out[0:D]).
// <<<UB, 256>>>
// ---------------------------------------------------------------------------
__device__ __forceinline__ float wg_at(int j, float inv_sum,
                                       const float* __restrict__ lw) {
    j &= (N - 1);
    float g = g_gate[j];
    return g * g_s[j] * inv_sum + (1.f - g) * lw[j];
}

__global__ void __launch_bounds__(256, 4) k_fused(const float* __restrict__ mem,
                                                  const float* __restrict__ lw,
                                                  float* __restrict__ out) {
    int t = threadIdx.x;
    int warp = t >> 5, lane = t & 31;
    __shared__ float red[8];
    __shared__ float bc;
    __shared__ float w_s[RPB];

    // phase 0: softmax denominator from 2048 partials
    float s = 0.f;
#pragma unroll
    for (int u = 0; u < RB / 256; u++) s += g_sp[t + 256 * u];
    s = warp_sum(s);
    if (lane == 0) red[warp] = s;
    __syncthreads();
    if (t == 0) {
        float v = 0.f;
#pragma unroll
        for (int i = 0; i < 8; i++) v += red[i];
        bc = 1.f / v;
    }
    __syncthreads();
    float inv_sum = bc;

    // phase 1: shift conv + pow for this block's 32 rows (warp 0 only)
    int base = blockIdx.x * RPB;
    if (t < RPB) {
        float a0 = g_dim5[2], a1 = g_dim5[3], a2 = g_dim5[4];
        float mm = fmaxf(a0, fmaxf(a1, a2));
        float e0 = expf(a0 - mm), e1 = expf(a1 - mm), e2 = expf(a2 - mm);
        float inv3 = 1.f / (e0 + e1 + e2);
        float gamma = g_dim5[1];
        int i = base + t;
        float wt = e0 * inv3 * wg_at(i - 1, inv_sum, lw)
                 + e1 * inv3 * wg_at(i,     inv_sum, lw)
                 + e2 * inv3 * wg_at(i + 1, inv_sum, lw);
        float wp = powf(wt, gamma);
        w_s[t] = wp;
        float p = warp_sum(wp);
        if (t == 0) g_pp[blockIdx.x] = p;     // pow-sum partial
    }
    __syncthreads();

    // grid sync: monotonic ticket counter (exactly UB arrivals per launch)
    if (t == 0) {
        __threadfence();
        unsigned ticket = atomicAdd(&g_arrive, 1u);
        unsigned target = (ticket / UB + 1u) * UB;
        while (atomicAdd(&g_arrive, 0u) < target) { }
    }
    __syncthreads();
    __threadfence();

    // phase 2: global pow-sum -> inv; weight out; memory update
    float v2 = g_pp[t] + g_pp[t + 256];
    v2 = warp_sum(v2);
    if (lane == 0) red[warp] = v2;
    __syncthreads();
    if (t == 0) {
        float v = 0.f;
#pragma unroll
        for (int i = 0; i < 8; i++) v += red[i];
        bc = 1.f / v;
    }
    __syncthreads();
    float inv = bc;

    if (t < RPB) out[D + base + t] = w_s[t] * inv;   // weight output

    float4* newm = reinterpret_cast<float4*>(out + D + N);
    const float4* m4 = reinterpret_cast<const float4*>(mem);
    float4 e4 = reinterpret_cast<const float4*>(g_erase)[t];
    float4 a4 = reinterpret_cast<const float4*>(g_add)[t];
    float4 acc = make_float4(0.f, 0.f, 0.f, 0.f);

#pragma unroll
    for (int r0 = 0; r0 < RPB; r0 += 8) {
        float4 m[8];
#pragma unroll
        for (int u = 0; u < 8; u++)
            m[u] = m4[(size_t)(base + r0 + u) * 256 + t];
#pragma unroll
        for (int u = 0; u < 8; u++) {
            float w = w_s[r0 + u] * inv;
            acc.x += w * m[u].x; acc.y += w * m[u].y;
            acc.z += w * m[u].z; acc.w += w * m[u].w;
            float4 nm;
            nm.x = m[u].x * (1.f - w * e4.x) + w * a4.x;
            nm.y = m[u].y * (1.f - w * e4.y) + w * a4.y;
            nm.z = m[u].z * (1.f - w * e4.z) + w * a4.z;
            nm.w = m[u].w * (1.f - w * e4.w) + w * a4.w;
            newm[(size_t)(base + r0 + u) * 256 + t] = nm;
        }
    }
    // memory_read: direct reduce into pre-zeroed out[0:D]
    atomicAdd(&out[4 * t + 0], acc.x);
    atomicAdd(&out[4 * t + 1], acc.y);
    atomicAdd(&out[4 * t + 2], acc.z);
    atomicAdd(&out[4 * t + 3], acc.w);
}

// ---------------------------------------------------------------------------
extern "C" void kernel_launch(void* const* d_in, const int* in_sizes, int n_in,
                              void* d_out, int out_size) {
    const float* hidden = (const float*)d_in[0];
    const float* lw     = (const float*)d_in[1];
    const float* mem    = (const float*)d_in[2];
    const float* Wd     = (const float*)d_in[3];
    const float* bd     = (const float*)d_in[4];
    const float* Wg     = (const float*)d_in[5];
    const float* bg     = (const float*)d_in[6];
    float* out = (float*)d_out;

    k_dim   <<<DIMSZ, 256>>>(Wd, hidden, bd, out);
    k_row   <<<RB, 256>>>(mem, Wg, hidden, bg);
    k_fused <<<UB, 256>>>(mem, lw, out);
}

// round 11
// speedup vs baseline: 1.5034x; 1.0034x over previous
#include <cuda_runtime.h>
#include <math.h>

#define H 2048
#define N 16384
#define D 1024
#define EPSV 1e-8f
#define DIMSZ (5 + 3*D)   // 3077
#define UB 512            // fused shift+update blocks
#define RPB (N / UB)      // 32 rows per fused block
#define RB (N / 8)        // k_row blocks: 8 warps x 1 row = 2048 blocks
#define TROWS 4           // rows per TMA tile
#define TBYTES (TROWS * D * 4)   // 16 KB
#define NTILES (RPB / TROWS)     // 8

// ---- scratch (__device__ globals; no allocs allowed) ----
__device__ float g_dim5[5];          // beta, gamma, shift logits
__device__ float g_k[D];
__device__ float g_erase[D];
__device__ float g_add[D];
__device__ float g_s[N];             // exp(beta*sim)  (no max-sub; bounded)
__device__ float g_gate[N];
__device__ float g_sp[RB];           // per-k_row-block exp partial sums
__device__ float g_pp[UB];           // per-fused-block pow-sum partials
__device__ unsigned g_arrive;        // monotonic grid-barrier ticket counter

__device__ __forceinline__ float warp_sum(float v) {
#pragma unroll
    for (int o = 16; o; o >>= 1) v += __shfl_xor_sync(0xffffffffu, v, o);
    return v;
}
__device__ __forceinline__ float dot4(float4 a, float4 b) {
    return a.x * b.x + a.y * b.y + a.z * b.z + a.w * b.w;
}
__device__ __forceinline__ unsigned smem_u32(const void* p) {
    return (unsigned)__cvta_generic_to_shared(p);
}

// ---------------------------------------------------------------------------
// dim_out = W_dim @ hidden + b_dim, warp-per-row (8 warps/block).
// h staged in smem; Wd batched 8-deep. First 4 blocks zero out[0:D].
// <<<(DIMSZ+7)/8, 256>>>
// ---------------------------------------------------------------------------
__global__ void __launch_bounds__(256) k_dim(const float* __restrict__ W,
                                             const float* __restrict__ h,
                                             const float* __restrict__ b,
                                             float* __restrict__ out) {
    __shared__ float4 sh[H / 4];     // 8 KB
    int t = threadIdx.x;
    {
        const float4* h4 = reinterpret_cast<const float4*>(h);
        sh[t] = h4[t];
        sh[t + 256] = h4[t + 256];
    }
    if (blockIdx.x < 4) out[blockIdx.x * 256 + t] = 0.f;   // memory_read init
    __syncthreads();

    int warp = t >> 5, lane = t & 31;
    int row = blockIdx.x * 8 + warp;
    if (row >= DIMSZ) return;

    const float4* w4 = reinterpret_cast<const float4*>(W + (size_t)row * H);
    float s = 0.f;
#pragma unroll
    for (int c = 0; c < 2; c++) {
        float4 wv[8];
#pragma unroll
        for (int u = 0; u < 8; u++) wv[u] = __ldcs(w4 + lane + 32 * (8 * c + u));
#pragma unroll
        for (int u = 0; u < 8; u++) s += dot4(wv[u], sh[lane + 32 * (8 * c + u)]);
    }
    s = warp_sum(s);
    if (lane == 0) {
        float v = s + b[row];
        if (row < 5)              g_dim5[row] = v;
        else if (row < 5 + D)     g_k[row - 5] = v;
        else if (row < 5 + 2*D)   g_erase[row - 5 - D] = v;
        else                      g_add[row - 5 - 2*D] = v;
    }
}

// ---------------------------------------------------------------------------
// Fused heavy pass: k and h staged in SMEM once per block; ONE ROW PER WARP.
// Emits per-block exp partial sums (g_sp). <<<RB, 256>>>
// ---------------------------------------------------------------------------
__global__ void __launch_bounds__(256) k_row(const float* __restrict__ mem,
                                             const float* __restrict__ Wg,
                                             const float* __restrict__ h,
                                             const float* __restrict__ bg) {
    __shared__ float4 sk[D / 4];     // 4 KB
    __shared__ float4 sh[H / 4];     // 8 KB
    __shared__ float sexp[8];
    int t = threadIdx.x;
    sk[t] = reinterpret_cast<const float4*>(g_k)[t];
    {
        const float4* h4 = reinterpret_cast<const float4*>(h);
        sh[t] = h4[t];
        sh[t + 256] = h4[t + 256];
    }
    __syncthreads();

    int warp = t >> 5, lane = t & 31;
    int row = blockIdx.x * 8 + warp;

    float k2 = 0.f;
#pragma unroll
    for (int u = 0; u < 8; u++) {
        float4 kk = sk[lane + 32 * u];
        k2 += dot4(kk, kk);
    }

    const float4* m4 = reinterpret_cast<const float4*>(mem + (size_t)row * D);
    float d1 = 0.f, d2 = 0.f;
#pragma unroll
    for (int c = 0; c < 2; c++) {
        float4 mv[4];
#pragma unroll
        for (int u = 0; u < 4; u++) mv[u] = m4[lane + 32 * (4 * c + u)];
#pragma unroll
        for (int u = 0; u < 4; u++) {
            float4 kk = sk[lane + 32 * (4 * c + u)];
            d1 += dot4(mv[u], kk);
            d2 += dot4(mv[u], mv[u]);
        }
    }
    const float4* w4 = reinterpret_cast<const float4*>(Wg + (size_t)row * H);
    float d3 = 0.f;
#pragma unroll
    for (int c = 0; c < 2; c++) {
        float4 wv[8];
#pragma unroll
        for (int u = 0; u < 8; u++) wv[u] = __ldcs(w4 + lane + 32 * (8 * c + u));
#pragma unroll
        for (int u = 0; u < 8; u++) {
            float4 xv = sh[lane + 32 * (8 * c + u)];
            d3 += dot4(wv[u], xv);
        }
    }
    d1 = warp_sum(d1); d2 = warp_sum(d2); d3 = warp_sum(d3); k2 = warp_sum(k2);
    if (lane == 0) {
        float sim = d1 / (sqrtf(d2) * sqrtf(k2) + EPSV);
        float ev = expf(g_dim5[0] * sim);      // bounded: |beta*sim| small
        g_s[row] = ev;
        sexp[warp] = ev;
        g_gate[row] = 1.f / (1.f + expf(-(d3 + bg[row])));
    }
    __syncthreads();
    if (t == 0) {
        float v = 0.f;
#pragma unroll
        for (int i = 0; i < 8; i++) v += sexp[i];
        g_sp[blockIdx.x] = v;                  // softmax denominator partial
    }
}

// ---------------------------------------------------------------------------
// FUSED shift + update + weight output + memory_read.
// Update loop reads `memory` via cp.async.bulk (TMA) double-buffered tiles;
// prologue loads issued BEFORE the grid barrier to hide its latency.
// <<<UB, 256>>>
// ---------------------------------------------------------------------------
__device__ __forceinline__ float wg_at(int j, float inv_sum,
                                       const float* __restrict__ lw) {
    j &= (N - 1);
    float g = g_gate[j];
    return g * g_s[j] * inv_sum + (1.f - g) * lw[j];
}

__global__ void __launch_bounds__(256, 4) k_fused(const float* __restrict__ mem,
                                                  const float* __restrict__ lw,
                                                  float* __restrict__ out) {
    __shared__ float4 buf[2][TROWS * 256];            // 2 x 16 KB
    __shared__ __align__(8) unsigned long long mbar[2];
    __shared__ float red[8];
    __shared__ float bc;
    __shared__ float w_s[RPB];

    int t = threadIdx.x;
    int warp = t >> 5, lane = t & 31;
    int base = blockIdx.x * RPB;
    const char* src = reinterpret_cast<const char*>(mem) + (size_t)base * D * 4;

    // mbarrier init + async-proxy fence
    if (t == 0) {
        unsigned m0 = smem_u32(&mbar[0]), m1 = smem_u32(&mbar[1]);
        asm volatile("mbarrier.init.shared.b64 [%0], 1;" :: "r"(m0) : "memory");
        asm volatile("mbarrier.init.shared.b64 [%0], 1;" :: "r"(m1) : "memory");
        asm volatile("fence.proxy.async.shared::cta;" ::: "memory");
    }
    __syncthreads();

    // prologue: issue tiles 0 and 1 (independent of other blocks)
    if (t == 0) {
#pragma unroll
        for (int p = 0; p < 2; p++) {
            unsigned mb = smem_u32(&mbar[p]);
            unsigned dst = smem_u32(&buf[p][0]);
            asm volatile("mbarrier.arrive.expect_tx.shared.b64 _, [%0], %1;"
                         :: "r"(mb), "r"((unsigned)TBYTES) : "memory");
            asm volatile("cp.async.bulk.shared::cluster.global.mbarrier::complete_tx::bytes"
                         " [%0], [%1], %2, [%3];"
                         :: "r"(dst), "l"(src + (size_t)p * TBYTES),
                            "r"((unsigned)TBYTES), "r"(mb) : "memory");
        }
    }

    // phase 0: softmax denominator from 2048 partials
    float s = 0.f;
#pragma unroll
    for (int u = 0; u < RB / 256; u++) s += g_sp[t + 256 * u];
    s = warp_sum(s);
    if (lane == 0) red[warp] = s;
    __syncthreads();
    if (t == 0) {
        float v = 0.f;
#pragma unroll
        for (int i = 0; i < 8; i++) v += red[i];
        bc = 1.f / v;
    }
    __syncthreads();
    float inv_sum = bc;

    // phase 1: shift conv + pow for this block's 32 rows (warp 0 only)
    if (t < RPB) {
        float a0 = g_dim5[2], a1 = g_dim5[3], a2 = g_dim5[4];
        float mm = fmaxf(a0, fmaxf(a1, a2));
        float e0 = expf(a0 - mm), e1 = expf(a1 - mm), e2 = expf(a2 - mm);
        float inv3 = 1.f / (e0 + e1 + e2);
        float gamma = g_dim5[1];
        int i = base + t;
        float wt = e0 * inv3 * wg_at(i - 1, inv_sum, lw)
                 + e1 * inv3 * wg_at(i,     inv_sum, lw)
                 + e2 * inv3 * wg_at(i + 1, inv_sum, lw);
        float wp = powf(wt, gamma);
        w_s[t] = wp;
        float p = warp_sum(wp);
        if (t == 0) g_pp[blockIdx.x] = p;     // pow-sum partial
    }
    __syncthreads();

    // grid sync: monotonic ticket counter (exactly UB arrivals per launch)
    if (t == 0) {
        __threadfence();
        unsigned ticket = atomicAdd(&g_arrive, 1u);
        unsigned target = (ticket / UB + 1u) * UB;
        while (atomicAdd(&g_arrive, 0u) < target) { }
    }
    __syncthreads();
    __threadfence();

    // phase 2: global pow-sum -> inv; weight out; memory update from smem
    float v2 = g_pp[t] + g_pp[t + 256];
    v2 = warp_sum(v2);
    if (lane == 0) red[warp] = v2;
    __syncthreads();
    if (t == 0) {
        float v = 0.f;
#pragma unroll
        for (int i = 0; i < 8; i++) v += red[i];
        bc = 1.f / v;
    }
    __syncthreads();
    float inv = bc;

    if (t < RPB) out[D + base + t] = w_s[t] * inv;   // weight output

    float4* newm = reinterpret_cast<float4*>(out + D + N);
    float4 e4 = reinterpret_cast<const float4*>(g_erase)[t];
    float4 a4 = reinterpret_cast<const float4*>(g_add)[t];
    float4 acc = make_float4(0.f, 0.f, 0.f, 0.f);
    int ph0 = 0, ph1 = 0;

#pragma unroll 1
    for (int tile = 0; tile < NTILES; tile++) {
        int cur = tile & 1;
        // wait for this tile's data
        {
            unsigned mb = smem_u32(&mbar[cur]);
            int ph = cur ? ph1 : ph0;
            asm volatile(
                "{\n\t.reg .pred p;\n"
                "WAIT_%=:\n\t"
                "mbarrier.try_wait.parity.shared.b64 p, [%0], %1;\n\t"
                "@!p bra WAIT_%=;\n\t}"
                :: "r"(mb), "r"(ph) : "memory");
            if (cur) ph1 ^= 1; else ph0 ^= 1;
        }
#pragma unroll
        for (int r = 0; r < TROWS; r++) {
            int row = base + tile * TROWS + r;
            float w = w_s[tile * TROWS + r] * inv;
            float4 m = buf[cur][r * 256 + t];
            acc.x += w * m.x; acc.y += w * m.y;
            acc.z += w * m.z; acc.w += w * m.w;
            float4 nm;
            nm.x = m.x * (1.f - w * e4.x) + w * a4.x;
            nm.y = m.y * (1.f - w * e4.y) + w * a4.y;
            nm.z = m.z * (1.f - w * e4.z) + w * a4.z;
            nm.w = m.w * (1.f - w * e4.w) + w * a4.w;
            newm[(size_t)row * 256 + t] = nm;
        }
        __syncthreads();   // all threads done reading buf[cur]
        if (t == 0 && tile + 2 < NTILES) {
            unsigned mb = smem_u32(&mbar[cur]);
            unsigned dst = smem_u32(&buf[cur][0]);
            asm volatile("mbarrier.arrive.expect_tx.shared.b64 _, [%0], %1;"
                         :: "r"(mb), "r"((unsigned)TBYTES) : "memory");
            asm volatile("cp.async.bulk.shared::cluster.global.mbarrier::complete_tx::bytes"
                         " [%0], [%1], %2, [%3];"
                         :: "r"(dst), "l"(src + (size_t)(tile + 2) * TBYTES),
                            "r"((unsigned)TBYTES), "r"(mb) : "memory");
        }
    }
    // memory_read: direct reduce into pre-zeroed out[0:D]
    atomicAdd(&out[4 * t + 0], acc.x);
    atomicAdd(&out[4 * t + 1], acc.y);
    atomicAdd(&out[4 * t + 2], acc.z);
    atomicAdd(&out[4 * t + 3], acc.w);
}

// ---------------------------------------------------------------------------
extern "C" void kernel_launch(void* const* d_in, const int* in_sizes, int n_in,
                              void* d_out, int out_size) {
    const float* hidden = (const float*)d_in[0];
    const float* lw     = (const float*)d_in[1];
    const float* mem    = (const float*)d_in[2];
    const float* Wd     = (const float*)d_in[3];
    const float* bd     = (const float*)d_in[4];
    const float* Wg     = (const float*)d_in[5];
    const float* bg     = (const float*)d_in[6];
    float* out = (float*)d_out;

    k_dim   <<<(DIMSZ + 7) / 8, 256>>>(Wd, hidden, bd, out);
    k_row   <<<RB, 256>>>(mem, Wg, hidden, bg);
    k_fused <<<UB, 256>>>(mem, lw, out);
}

// round 12
// speedup vs baseline: 1.5396x; 1.0240x over previous
#include <cuda_runtime.h>
#include <math.h>

#define H 2048
#define N 16384
#define D 1024
#define EPSV 1e-8f
#define DIMSZ (5 + 3*D)   // 3077
#define UB 512            // fused shift+update blocks
#define RPB (N / UB)      // 32 rows per fused block
#define RB (N / 8)        // gate/sim blocks: 8 warps x 1 row = 2048 blocks
#define TROWS 4           // rows per TMA tile
#define TBYTES (TROWS * D * 4)   // 16 KB
#define NTILES (RPB / TROWS)     // 8

// ---- scratch (__device__ globals; no allocs allowed) ----
__device__ float g_dim5[5];          // beta, gamma, shift logits
__device__ float g_k[D];
__device__ float g_erase[D];
__device__ float g_add[D];
__device__ float g_s[N];             // exp(beta*sim)  (no max-sub; bounded)
__device__ float g_gate[N];
__device__ float g_sp[RB];           // per-sim-block exp partial sums
__device__ float g_pp[UB];           // per-fused-block pow-sum partials
__device__ unsigned g_arrive;        // monotonic grid-barrier ticket counter

__device__ __forceinline__ float warp_sum(float v) {
#pragma unroll
    for (int o = 16; o; o >>= 1) v += __shfl_xor_sync(0xffffffffu, v, o);
    return v;
}
__device__ __forceinline__ float dot4(float4 a, float4 b) {
    return a.x * b.x + a.y * b.y + a.z * b.z + a.w * b.w;
}
__device__ __forceinline__ unsigned smem_u32(const void* p) {
    return (unsigned)__cvta_generic_to_shared(p);
}

// ---------------------------------------------------------------------------
// dim_out = W_dim @ hidden + b_dim, warp-per-row (8 warps/block).
// First 4 blocks zero out[0:D]. <<<(DIMSZ+7)/8, 256>>>  [stream 0]
// ---------------------------------------------------------------------------
__global__ void __launch_bounds__(256) k_dim(const float* __restrict__ W,
                                             const float* __restrict__ h,
                                             const float* __restrict__ b,
                                             float* __restrict__ out) {
    __shared__ float4 sh[H / 4];     // 8 KB
    int t = threadIdx.x;
    {
        const float4* h4 = reinterpret_cast<const float4*>(h);
        sh[t] = h4[t];
        sh[t + 256] = h4[t + 256];
    }
    if (blockIdx.x < 4) out[blockIdx.x * 256 + t] = 0.f;   // memory_read init
    __syncthreads();

    int warp = t >> 5, lane = t & 31;
    int row = blockIdx.x * 8 + warp;
    if (row >= DIMSZ) return;

    const float4* w4 = reinterpret_cast<const float4*>(W + (size_t)row * H);
    float s = 0.f;
#pragma unroll
    for (int c = 0; c < 2; c++) {
        float4 wv[8];
#pragma unroll
        for (int u = 0; u < 8; u++) wv[u] = __ldcs(w4 + lane + 32 * (8 * c + u));
#pragma unroll
        for (int u = 0; u < 8; u++) s += dot4(wv[u], sh[lane + 32 * (8 * c + u)]);
    }
    s = warp_sum(s);
    if (lane == 0) {
        float v = s + b[row];
        if (row < 5)              g_dim5[row] = v;
        else if (row < 5 + D)     g_k[row - 5] = v;
        else if (row < 5 + 2*D)   g_erase[row - 5 - D] = v;
        else                      g_add[row - 5 - 2*D] = v;
    }
}

// ---------------------------------------------------------------------------
// Gate GEMV (INDEPENDENT of k_dim): g_gate = sigmoid(Wg @ h + bg).
// Warp-per-row, h in smem, Wg streamed 8-deep. <<<RB, 256>>>  [stream 1]
// ---------------------------------------------------------------------------
__global__ void __launch_bounds__(256) k_gate(const float* __restrict__ Wg,
                                              const float* __restrict__ h,
                                              const float* __restrict__ bg) {
    __shared__ float4 sh[H / 4];     // 8 KB
    int t = threadIdx.x;
    {
        const float4* h4 = reinterpret_cast<const float4*>(h);
        sh[t] = h4[t];
        sh[t + 256] = h4[t + 256];
    }
    __syncthreads();

    int warp = t >> 5, lane = t & 31;
    int row = blockIdx.x * 8 + warp;
    const float4* w4 = reinterpret_cast<const float4*>(Wg + (size_t)row * H);
    float d3 = 0.f;
#pragma unroll
    for (int c = 0; c < 2; c++) {
        float4 wv[8];
#pragma unroll
        for (int u = 0; u < 8; u++) wv[u] = __ldcs(w4 + lane + 32 * (8 * c + u));
#pragma unroll
        for (int u = 0; u < 8; u++) d3 += dot4(wv[u], sh[lane + 32 * (8 * c + u)]);
    }
    d3 = warp_sum(d3);
    if (lane == 0)
        g_gate[row] = 1.f / (1.f + expf(-(d3 + bg[row])));
}

// ---------------------------------------------------------------------------
// Similarity pass (depends on k_dim): dot(mem_i,k), ||mem_i||^2, ||k||^2
// -> g_s[i] = exp(beta*cos_sim), per-block partials g_sp.
// Warp-per-row, k in smem, mem 8-deep batched. <<<RB, 256>>>  [stream 0]
// ---------------------------------------------------------------------------
__global__ void __launch_bounds__(256) k_sim(const float* __restrict__ mem) {
    __shared__ float4 sk[D / 4];     // 4 KB
    __shared__ float sexp[8];
    int t = threadIdx.x;
    sk[t] = reinterpret_cast<const float4*>(g_k)[t];
    __syncthreads();

    int warp = t >> 5, lane = t & 31;
    int row = blockIdx.x * 8 + warp;

    const float4* m4 = reinterpret_cast<const float4*>(mem + (size_t)row * D);
    float4 mv[8];
#pragma unroll
    for (int u = 0; u < 8; u++) mv[u] = m4[lane + 32 * u];

    float d1 = 0.f, d2 = 0.f, k2 = 0.f;
#pragma unroll
    for (int u = 0; u < 8; u++) {
        float4 kk = sk[lane + 32 * u];
        d1 += dot4(mv[u], kk);
        d2 += dot4(mv[u], mv[u]);
        k2 += dot4(kk, kk);
    }
    d1 = warp_sum(d1); d2 = warp_sum(d2); k2 = warp_sum(k2);
    if (lane == 0) {
        float sim = d1 / (sqrtf(d2) * sqrtf(k2) + EPSV);
        float ev = expf(g_dim5[0] * sim);      // bounded: |beta*sim| small
        g_s[row] = ev;
        sexp[warp] = ev;
    }
    __syncthreads();
    if (t == 0) {
        float v = 0.f;
#pragma unroll
        for (int i = 0; i < 8; i++) v += sexp[i];
        g_sp[blockIdx.x] = v;                  // softmax denominator partial
    }
}

// ---------------------------------------------------------------------------
// FUSED shift + update + weight output + memory_read.
// Update loop reads `memory` via cp.async.bulk double-buffered tiles;
// prologue loads issued BEFORE the grid barrier. <<<UB, 256>>>
// ---------------------------------------------------------------------------
__device__ __forceinline__ float wg_at(int j, float inv_sum,
                                       const float* __restrict__ lw) {
    j &= (N - 1);
    float g = g_gate[j];
    return g * g_s[j] * inv_sum + (1.f - g) * lw[j];
}

__global__ void __launch_bounds__(256, 4) k_fused(const float* __restrict__ mem,
                                                  const float* __restrict__ lw,
                                                  float* __restrict__ out) {
    __shared__ float4 buf[2][TROWS * 256];            // 2 x 16 KB
    __shared__ __align__(8) unsigned long long mbar[2];
    __shared__ float red[8];
    __shared__ float bc;
    __shared__ float w_s[RPB];

    int t = threadIdx.x;
    int warp = t >> 5, lane = t & 31;
    int base = blockIdx.x * RPB;
    const char* src = reinterpret_cast<const char*>(mem) + (size_t)base * D * 4;

    if (t == 0) {
        unsigned m0 = smem_u32(&mbar[0]), m1 = smem_u32(&mbar[1]);
        asm volatile("mbarrier.init.shared.b64 [%0], 1;" :: "r"(m0) : "memory");
        asm volatile("mbarrier.init.shared.b64 [%0], 1;" :: "r"(m1) : "memory");
        asm volatile("fence.proxy.async.shared::cta;" ::: "memory");
    }
    __syncthreads();

    // prologue: issue tiles 0 and 1
    if (t == 0) {
#pragma unroll
        for (int p = 0; p < 2; p++) {
            unsigned mb = smem_u32(&mbar[p]);
            unsigned dst = smem_u32(&buf[p][0]);
            asm volatile("mbarrier.arrive.expect_tx.shared.b64 _, [%0], %1;"
                         :: "r"(mb), "r"((unsigned)TBYTES) : "memory");
            asm volatile("cp.async.bulk.shared::cluster.global.mbarrier::complete_tx::bytes"
                         " [%0], [%1], %2, [%3];"
                         :: "r"(dst), "l"(src + (size_t)p * TBYTES),
                            "r"((unsigned)TBYTES), "r"(mb) : "memory");
        }
    }

    // phase 0: softmax denominator from 2048 partials
    float s = 0.f;
#pragma unroll
    for (int u = 0; u < RB / 256; u++) s += g_sp[t + 256 * u];
    s = warp_sum(s);
    if (lane == 0) red[warp] = s;
    __syncthreads();
    if (t == 0) {
        float v = 0.f;
#pragma unroll
        for (int i = 0; i < 8; i++) v += red[i];
        bc = 1.f / v;
    }
    __syncthreads();
    float inv_sum = bc;

    // phase 1: shift conv + pow for this block's 32 rows (warp 0 only)
    if (t < RPB) {
        float a0 = g_dim5[2], a1 = g_dim5[3], a2 = g_dim5[4];
        float mm = fmaxf(a0, fmaxf(a1, a2));
        float e0 = expf(a0 - mm), e1 = expf(a1 - mm), e2 = expf(a2 - mm);
        float inv3 = 1.f / (e0 + e1 + e2);
        float gamma = g_dim5[1];
        int i = base + t;
        float wt = e0 * inv3 * wg_at(i - 1, inv_sum, lw)
                 + e1 * inv3 * wg_at(i,     inv_sum, lw)
                 + e2 * inv3 * wg_at(i + 1, inv_sum, lw);
        float wp = powf(wt, gamma);
        w_s[t] = wp;
        float p = warp_sum(wp);
        if (t == 0) g_pp[blockIdx.x] = p;     // pow-sum partial
    }
    __syncthreads();

    // grid sync: monotonic ticket counter (exactly UB arrivals per launch)
    if (t == 0) {
        __threadfence();
        unsigned ticket = atomicAdd(&g_arrive, 1u);
        unsigned target = (ticket / UB + 1u) * UB;
        while (atomicAdd(&g_arrive, 0u) < target) { }
    }
    __syncthreads();
    __threadfence();

    // phase 2: global pow-sum -> inv; weight out; memory update from smem
    float v2 = g_pp[t] + g_pp[t + 256];
    v2 = warp_sum(v2);
    if (lane == 0) red[warp] = v2;
    __syncthreads();
    if (t == 0) {
        float v = 0.f;
#pragma unroll
        for (int i = 0; i < 8; i++) v += red[i];
        bc = 1.f / v;
    }
    __syncthreads();
    float inv = bc;

    if (t < RPB) out[D + base + t] = w_s[t] * inv;   // weight output

    float4* newm = reinterpret_cast<float4*>(out + D + N);
    float4 e4 = reinterpret_cast<const float4*>(g_erase)[t];
    float4 a4 = reinterpret_cast<const float4*>(g_add)[t];
    float4 acc = make_float4(0.f, 0.f, 0.f, 0.f);
    int ph0 = 0, ph1 = 0;

#pragma unroll 1
    for (int tile = 0; tile < NTILES; tile++) {
        int cur = tile & 1;
        {
            unsigned mb = smem_u32(&mbar[cur]);
            int ph = cur ? ph1 : ph0;
            asm volatile(
                "{\n\t.reg .pred p;\n"
                "WAIT_%=:\n\t"
                "mbarrier.try_wait.parity.shared.b64 p, [%0], %1;\n\t"
                "@!p bra WAIT_%=;\n\t}"
                :: "r"(mb), "r"(ph) : "memory");
            if (cur) ph1 ^= 1; else ph0 ^= 1;
        }
#pragma unroll
        for (int r = 0; r < TROWS; r++) {
            int row = base + tile * TROWS + r;
            float w = w_s[tile * TROWS + r] * inv;
            float4 m = buf[cur][r * 256 + t];
            acc.x += w * m.x; acc.y += w * m.y;
            acc.z += w * m.z; acc.w += w * m.w;
            float4 nm;
            nm.x = m.x * (1.f - w * e4.x) + w * a4.x;
            nm.y = m.y * (1.f - w * e4.y) + w * a4.y;
            nm.z = m.z * (1.f - w * e4.z) + w * a4.z;
            nm.w = m.w * (1.f - w * e4.w) + w * a4.w;
            newm[(size_t)row * 256 + t] = nm;
        }
        __syncthreads();
        if (t == 0 && tile + 2 < NTILES) {
            unsigned mb = smem_u32(&mbar[cur]);
            unsigned dst = smem_u32(&buf[cur][0]);
            asm volatile("mbarrier.arrive.expect_tx.shared.b64 _, [%0], %1;"
                         :: "r"(mb), "r"((unsigned)TBYTES) : "memory");
            asm volatile("cp.async.bulk.shared::cluster.global.mbarrier::complete_tx::bytes"
                         " [%0], [%1], %2, [%3];"
                         :: "r"(dst), "l"(src + (size_t)(tile + 2) * TBYTES),
                            "r"((unsigned)TBYTES), "r"(mb) : "memory");
        }
    }
    // memory_read: direct reduce into pre-zeroed out[0:D]
    atomicAdd(&out[4 * t + 0], acc.x);
    atomicAdd(&out[4 * t + 1], acc.y);
    atomicAdd(&out[4 * t + 2], acc.z);
    atomicAdd(&out[4 * t + 3], acc.w);
}

// ---------------------------------------------------------------------------
// DAG:   [k_dim -> k_sim]  (stream 0)
//        [k_gate]          (stream 1, forked/joined via events)
//        -> k_fused        (stream 0)
// Streams/events are host resources (no device memory), lazily created once.
// ---------------------------------------------------------------------------
extern "C" void kernel_launch(void* const* d_in, const int* in_sizes, int n_in,
                              void* d_out, int out_size) {
    const float* hidden = (const float*)d_in[0];
    const float* lw     = (const float*)d_in[1];
    const float* mem    = (const float*)d_in[2];
    const float* Wd     = (const float*)d_in[3];
    const float* bd     = (const float*)d_in[4];
    const float* Wg     = (const float*)d_in[5];
    const float* bg     = (const float*)d_in[6];
    float* out = (float*)d_out;

    static cudaStream_t s1 = nullptr;
    static cudaEvent_t ev_fork = nullptr, ev_join = nullptr;
    if (s1 == nullptr) {
        cudaStreamCreateWithFlags(&s1, cudaStreamNonBlocking);
        cudaEventCreateWithFlags(&ev_fork, cudaEventDisableTiming);
        cudaEventCreateWithFlags(&ev_join, cudaEventDisableTiming);
    }

    // fork: gate GEMV (independent) on s1
    cudaEventRecord(ev_fork, 0);
    cudaStreamWaitEvent(s1, ev_fork, 0);
    k_gate<<<RB, 256, 0, s1>>>(Wg, hidden, bg);
    cudaEventRecord(ev_join, s1);

    // main branch: dim -> sim
    k_dim<<<(DIMSZ + 7) / 8, 256>>>(Wd, hidden, bd, out);
    k_sim<<<RB, 256>>>(mem);

    // join, then fused epilogue
    cudaStreamWaitEvent((cudaStream_t)0, ev_join, 0);
    k_fused<<<UB, 256>>>(mem, lw, out);
}